// round 17
// baseline (speedup 1.0000x reference)
#include <cuda_runtime.h>
#include <cuda_bf16.h>

// ---------------------------------------------------------------------------
// NDCG loss, N = 16,777,216 (general N supported up to MAXG*EPB).
// Pass 1: score --cp.async--> shared tile -> bitmask + per-block counts.
// Pass 2: predict + bitmask -> unified branch-free term. Issue-optimized:
//         full-tile fast path (no per-element guards), nibble mask decode,
//         parallel rank partial-sums, ops balanced toward the FMA pipe.
//         Fenced last-block final reduction (no third launch).
// ---------------------------------------------------------------------------

#define EPB 8192            // elements per block (256 thr * 32 elem)
#define EPW 1024            // elements per warp
#define MAXG 4096           // max blocks supported by static scratch

__device__ unsigned int g_mask[MAXG * 256];   // 1 bit per element
__device__ int          g_counts[MAXG];       // positives per block
__device__ float        g_partials[MAXG];     // per-block loss partials
__device__ int          g_done = 0;           // last-block counter (self-reset)

// ---------------------------------------------------------------------------
__global__ __launch_bounds__(256, 4) void k_mask(const float* __restrict__ score,
                                                 int N) {
    __shared__ float sbuf[EPB];               // 32 KB tile
    const int tid  = threadIdx.x;
    const int warp = tid >> 5, lane = tid & 31;
    const int blkBase = blockIdx.x * EPB;

    if (blkBase + EPB <= N) {
        // Full tile: 8 x 16B cp.async per thread = 2048 chunks in flight.
        #pragma unroll
        for (int t = 0; t < 8; ++t) {
            const int off = t * 1024 + tid * 4;
            unsigned saddr = (unsigned)__cvta_generic_to_shared(sbuf + off);
            const float* g = score + blkBase + off;
            asm volatile("cp.async.cg.shared.global [%0], [%1], 16;\n"
                         :: "r"(saddr), "l"(g));
        }
        asm volatile("cp.async.commit_group;\n");
        asm volatile("cp.async.wait_group 0;\n");
    } else {
        for (int i = tid; i < EPB; i += 256) {
            int idx = blkBase + i;
            sbuf[i] = (idx < N) ? score[idx] : 0.0f;
        }
    }
    __syncthreads();

    // Warp covers EPW=1024 elements -> 32 mask words; lane L owns word L.
    unsigned myword = 0;
    #pragma unroll
    for (int t = 0; t < 32; ++t) {
        float v = sbuf[warp * 1024 + t * 32 + lane];
        unsigned b = __ballot_sync(0xffffffffu, v > 0.0f);
        if (lane == t) myword = b;
    }
    g_mask[(blockIdx.x << 8) + (warp << 5) + lane] = myword;

    int c = __popc(myword);
    #pragma unroll
    for (int o = 16; o; o >>= 1) c += __shfl_xor_sync(0xffffffffu, c, o);

    __shared__ int sc[8];
    if (lane == 0) sc[warp] = c;
    __syncthreads();
    if (threadIdx.x == 0) {
        int t = 0;
        #pragma unroll
        for (int w = 0; w < 8; ++w) t += sc[w];
        g_counts[blockIdx.x] = t;
    }
}

// ---------------------------------------------------------------------------
__global__ __launch_bounds__(256, 4) void k_loss(const float* __restrict__ pred,
                                                 float* __restrict__ out,
                                                 int N, int G) {
    const int tid  = threadIdx.x;
    const int warp = tid >> 5, lane = tid & 31;

    // --- exclusive block prefix of positives + total P (L2-hot counts) ---
    int pre = 0, tot = 0;
    for (int i = tid; i < G; i += 256) {
        int c = g_counts[i];
        tot += c;
        pre += (i < (int)blockIdx.x) ? c : 0;
    }
    #pragma unroll
    for (int o = 16; o; o >>= 1) {
        pre += __shfl_xor_sync(0xffffffffu, pre, o);
        tot += __shfl_xor_sync(0xffffffffu, tot, o);
    }
    __shared__ int spre[8], stot[8], wsum[8];
    if (lane == 0) { spre[warp] = pre; stot[warp] = tot; }
    __syncthreads();
    int blockPre = 0, P = 0;
    #pragma unroll
    for (int w = 0; w < 8; ++w) { blockPre += spre[w]; P += stot[w]; }

    // --- per-warp mask words + intra-warp positive prefix via popc scan ---
    const int base = blockIdx.x * EPB + warp * EPW;
    unsigned myword = g_mask[(blockIdx.x << 8) + (warp << 5) + lane];
    int wc  = __popc(myword);
    int inc = wc;
    #pragma unroll
    for (int o = 1; o < 32; o <<= 1) {
        int t = __shfl_up_sync(0xffffffffu, inc, o);
        if (lane >= o) inc += t;
    }
    int exc = inc - wc;                 // positives before word 'lane' in warp
    if (lane == 31) wsum[warp] = inc;   // warp total
    __syncthreads();
    int warpBase = blockPre;
    for (int w = 0; w < warp; ++w) warpBase += wsum[w];

    const float Pf     = (float)P;
    const float invP   = 1.0f / Pf;         // s value at positives
    const float PbBase = Pf + (float)base + (float)(lane * 4) + 2.0f;

    float acc = 0.0f;
    const bool fullTile = (blockIdx.x * EPB + EPB <= N);

    if (fullTile) {
        // ---- all 8 float4 loads first: 32 x 128B lines in flight/warp ----
        float4 pv[8];
        #pragma unroll
        for (int t = 0; t < 8; ++t)
            pv[t] = __ldcs(reinterpret_cast<const float4*>(
                               pred + base + t * 128 + lane * 4));

        #pragma unroll
        for (int j = 0; j < 8; ++j) {
            const int wl = j * 4 + (lane >> 3);
            const unsigned w = __shfl_sync(0xffffffffu, myword, wl);
            const int pe     = __shfl_sync(0xffffffffu, exc,    wl);
            const int bit0   = (lane & 7) * 4;
            const int kbase  = warpBase + pe + __popc(w & ((1u << bit0) - 1u));
            const unsigned nib = (w >> bit0) & 0xFu;          // once per quad

            // parallel float ranks (short critical path)
            const float f0 = (nib & 1u) ? 1.0f : 0.0f;
            const float f1 = (nib & 2u) ? 1.0f : 0.0f;
            const float f2 = (nib & 4u) ? 1.0f : 0.0f;
            const float k0 = (float)kbase;                    // one I2F/quad
            const float p01  = f0 + f1;
            const float p012 = p01 + f2;
            const float kk[4]  = {k0, k0 + f0, k0 + p01, k0 + p012};
            const float ff[4]  = {f0, f1, f2, (nib & 8u) ? 1.0f : 0.0f};
            const float Pb0 = PbBase + (float)(j * 128);
            const float pvals[4] = {pv[j].x, pv[j].y, pv[j].z, pv[j].w};

            #pragma unroll
            for (int c = 0; c < 4; ++c) {
                const bool pos = (nib >> c) & 1u;
                // pos: A=k+1=kk+2, C=log2(A), d=(p*C - invP*A)/(A*C)
                // neg: A=P+m+1=(Pb0+c)-kk, C=1,  d= p/A
                const float A   = pos ? (kk[c] + 2.0f)
                                      : ((Pb0 + (float)c) - kk[c]);
                const float L   = __log2f(A);
                const float C   = pos ? L : 1.0f;
                const float t2  = (ff[c] * invP) * A;   // FMA pipe, no SEL
                const float num = fmaf(pvals[c], C, -t2);
                const float d   = __fdividef(num, A * C);
                acc = fmaf(d, d, acc);
            }
        }
    } else {
        // Tail fallback (not hit at N = 2^24): guarded scalar path.
        for (int j = 0; j < 8; ++j) {
            const int wl = j * 4 + (lane >> 3);
            const unsigned w = __shfl_sync(0xffffffffu, myword, wl);
            const int pe     = __shfl_sync(0xffffffffu, exc,    wl);
            const int bit0   = (lane & 7) * 4;
            int kb = warpBase + pe + __popc(w & ((1u << bit0) - 1u));
            for (int c = 0; c < 4; ++c) {
                const int idx = base + j * 128 + lane * 4 + c;
                if (idx < N) {
                    const bool pos = (w >> (bit0 + c)) & 1u;
                    const float p = pred[idx];
                    const float A = pos ? (float)(kb + 2)
                                        : (Pf + (float)(idx + 2 - kb));
                    const float C = pos ? __log2f(A) : 1.0f;
                    const float sel = pos ? invP : 0.0f;
                    const float num = p * C - sel * A;
                    const float d = __fdividef(num, A * C);
                    acc += d * d;
                    kb += pos ? 1 : 0;
                }
            }
        }
    }

    #pragma unroll
    for (int o = 16; o; o >>= 1) acc += __shfl_xor_sync(0xffffffffu, acc, o);
    __shared__ float sacc[8];
    __shared__ bool  sIsLast;
    if (lane == 0) sacc[warp] = acc;
    __syncthreads();
    if (tid == 0) {
        float t = 0.0f;
        #pragma unroll
        for (int w = 0; w < 8; ++w) t += sacc[w];
        g_partials[blockIdx.x] = t;
        __threadfence();                       // publish partial
        int old = atomicAdd(&g_done, 1);
        sIsLast = (old == G - 1);
    }
    __syncthreads();

    // ---- last block reduces (index-ordered -> deterministic sum) ----
    if (sIsLast) {
        __threadfence();                       // acquire all partials
        float a = 0.0f;
        for (int i = tid; i < G; i += 256) a += g_partials[i];
        #pragma unroll
        for (int o = 16; o; o >>= 1) a += __shfl_xor_sync(0xffffffffu, a, o);
        if (lane == 0) sacc[warp] = a;
        __syncthreads();
        if (tid == 0) {
            float t = 0.0f;
            #pragma unroll
            for (int w = 0; w < 8; ++w) t += sacc[w];
            out[0] = t;
            g_done = 0;                        // reset for next graph replay
        }
    }
}

// ---------------------------------------------------------------------------
extern "C" void kernel_launch(void* const* d_in, const int* in_sizes, int n_in,
                              void* d_out, int out_size) {
    const float* pred  = (const float*)d_in[0];  // predict_score
    const float* score = (const float*)d_in[1];  // score (0/1)
    int N = in_sizes[0];
    int G = (N + EPB - 1) / EPB;
    if (G > MAXG) G = MAXG;   // problem size is 2^24 -> G = 2048

    k_mask<<<G, 256>>>(score, N);
    k_loss<<<G, 256>>>(pred, (float*)d_out, N, G);
}